// round 2
// baseline (speedup 1.0000x reference)
#include <cuda_runtime.h>
#include <cuda_bf16.h>
#include <math.h>

#define NN     50000
#define EE     400000
#define ETOT   (EE + NN)     // edges + self loops
#define FIN    165
#define HID    256
#define NHEADS 8
#define FMAX   2048          // layer2: 8 heads * 256

// ---------------- scratch (device globals; no allocation) ----------------
__device__ float g_h    [NN * HID];        // current node features
__device__ float g_ht   [NN * FMAX];       // transformed features (per layer)
__device__ float g_ssrc [NN * NHEADS];
__device__ float g_sdst [NN * NHEADS];
__device__ float g_den  [NN * NHEADS];     // 1/denominator per (node, head)
__device__ float g_alpha[ETOT * NHEADS];   // exp(e - m), CSR slot order
__device__ float g_c1   [NN * 128];        // classifier hidden
// CSR
__device__ int   g_deg   [NN];
__device__ int   g_rowptr[NN + 1];
__device__ int   g_wpos  [NN];
__device__ int   g_esrc  [ETOT];

__device__ __forceinline__ float leaky(float v) { return v > 0.f ? v : 0.2f * v; }

// ---------------- SGEMM: C[M,Nc] = A[M,K] @ B[K,Nc] (+bias, act) --------
// 128x128 block tile, BK=8, 256 threads, 8x8 per thread.
__global__ void __launch_bounds__(256)
sgemm128(const float* __restrict__ A, const float* __restrict__ B,
         float* __restrict__ C, int M, int K, int Nc,
         const float* __restrict__ bias, int act /*0 none, 1 relu*/) {
    __shared__ float As[8][128];   // As[k][m]
    __shared__ float Bs[8][128];   // Bs[k][n]

    const int tid  = threadIdx.x;
    const int brow = blockIdx.y * 128;
    const int bcol = blockIdx.x * 128;
    const int trow = (tid / 16) * 8;
    const int tcol = (tid % 16) * 8;

    const int arow = tid / 2;            // 0..127
    const int acol = (tid % 2) * 4;      // 0 or 4 (k within tile)
    const int brw  = tid / 32;           // 0..7  (k within tile)
    const int bcl  = (tid % 32) * 4;     // 0..124

    float acc[8][8];
#pragma unroll
    for (int i = 0; i < 8; i++)
#pragma unroll
        for (int j = 0; j < 8; j++) acc[i][j] = 0.f;

    for (int k0 = 0; k0 < K; k0 += 8) {
#pragma unroll
        for (int i = 0; i < 4; i++) {
            int gr = brow + arow, gc = k0 + acol + i;
            As[acol + i][arow] = (gr < M && gc < K) ? A[(size_t)gr * K + gc] : 0.f;
        }
#pragma unroll
        for (int i = 0; i < 4; i++) {
            int gr = k0 + brw, gc = bcol + bcl + i;
            Bs[brw][bcl + i] = (gr < K && gc < Nc) ? B[(size_t)gr * Nc + gc] : 0.f;
        }
        __syncthreads();
#pragma unroll
        for (int kk = 0; kk < 8; kk++) {
            float a[8], b[8];
#pragma unroll
            for (int i = 0; i < 8; i++) a[i] = As[kk][trow + i];
#pragma unroll
            for (int j = 0; j < 8; j++) b[j] = Bs[kk][tcol + j];
#pragma unroll
            for (int i = 0; i < 8; i++)
#pragma unroll
                for (int j = 0; j < 8; j++) acc[i][j] += a[i] * b[j];
        }
        __syncthreads();
    }

#pragma unroll
    for (int i = 0; i < 8; i++) {
        int gr = brow + trow + i;
        if (gr >= M) continue;
#pragma unroll
        for (int j = 0; j < 8; j++) {
            int gc = bcol + tcol + j;
            if (gc >= Nc) continue;
            float v = acc[i][j];
            if (bias) v += bias[gc];
            if (act == 1) v = v > 0.f ? v : 0.f;
            C[(size_t)gr * Nc + gc] = v;
        }
    }
}

// ---------------- CSR build ----------------
__global__ void deg_kernel(const int* __restrict__ ei) {
    int e = blockIdx.x * blockDim.x + threadIdx.x;
    if (e >= ETOT) return;
    int t = (e < EE) ? ei[EE + e] : (e - EE);
    atomicAdd(&g_deg[t], 1);
}

// single-block chunked exclusive scan of g_deg -> g_rowptr, g_wpos
__global__ void scan_kernel() {
    __shared__ int sh[1024];
    __shared__ int running;
    if (threadIdx.x == 0) running = 0;
    __syncthreads();
    for (int base = 0; base < NN; base += 1024) {
        int i = base + (int)threadIdx.x;
        int v = (i < NN) ? g_deg[i] : 0;
        sh[threadIdx.x] = v;
        __syncthreads();
        for (int off = 1; off < 1024; off <<= 1) {
            int t = (threadIdx.x >= off) ? sh[threadIdx.x - off] : 0;
            __syncthreads();
            sh[threadIdx.x] += t;
            __syncthreads();
        }
        int incl = sh[threadIdx.x];
        int excl = incl - v + running;
        if (i < NN) { g_rowptr[i] = excl; g_wpos[i] = excl; }
        __syncthreads();
        if (threadIdx.x == 0) running += sh[1023];
        __syncthreads();
    }
    if (threadIdx.x == 0) g_rowptr[NN] = running;
}

__global__ void scatter_kernel(const int* __restrict__ ei) {
    int e = blockIdx.x * blockDim.x + threadIdx.x;
    if (e >= ETOT) return;
    int s = (e < EE) ? ei[e]      : (e - EE);
    int t = (e < EE) ? ei[EE + e] : (e - EE);
    int slot = atomicAdd(&g_wpos[t], 1);
    g_esrc[slot] = s;
}

// ---------------- per-(node,head) attention scores ----------------
__global__ void scores_kernel(const float* __restrict__ asrc,
                              const float* __restrict__ adst, int d) {
    int gt   = blockIdx.x * blockDim.x + threadIdx.x;
    int warp = gt >> 5;
    int lane = gt & 31;
    if (warp >= NN * NHEADS) return;
    int n = warp / NHEADS, h = warp % NHEADS;
    const float* row = g_ht + (size_t)n * NHEADS * d + (size_t)h * d;
    float s1 = 0.f, s2 = 0.f;
    for (int i = lane; i < d; i += 32) {
        float v = row[i];
        s1 += v * asrc[h * d + i];
        s2 += v * adst[h * d + i];
    }
#pragma unroll
    for (int o = 16; o; o >>= 1) {
        s1 += __shfl_xor_sync(0xFFFFFFFFu, s1, o);
        s2 += __shfl_xor_sync(0xFFFFFFFFu, s2, o);
    }
    if (lane == 0) {
        g_ssrc[n * NHEADS + h] = s1;
        g_sdst[n * NHEADS + h] = s2;
    }
}

// ---------------- segment softmax, atomic-free ----------------
// one thread per (node, head); walks CSR edge list twice.
__global__ void softmax_csr() {
    int idx = blockIdx.x * blockDim.x + threadIdx.x;
    if (idx >= NN * NHEADS) return;
    int n = idx / NHEADS, h = idx % NHEADS;
    int beg = g_rowptr[n], end = g_rowptr[n + 1];
    float sd = g_sdst[idx];
    float mx = -1e30f;
    for (int j = beg; j < end; j++) {
        float v = leaky(g_ssrc[g_esrc[j] * NHEADS + h] + sd);
        mx = fmaxf(mx, v);
    }
    float den = 0.f;
    for (int j = beg; j < end; j++) {
        float v  = leaky(g_ssrc[g_esrc[j] * NHEADS + h] + sd);
        float ex = expf(v - mx);
        g_alpha[(size_t)j * NHEADS + h] = ex;
        den += ex;
    }
    g_den[idx] = 1.f / den;   // every node has a self-loop -> den > 0
}

// ---------------- aggregation: F=256 (d=32), fused bias + ELU -----------
// one block (256 threads) per dst node; thread owns one feature; plain stores.
__global__ void __launch_bounds__(256)
aggr_csr_256(const float* __restrict__ bias) {
    int n   = blockIdx.x;
    int tid = threadIdx.x;
    int h   = tid >> 5;                 // d = 32
    int beg = g_rowptr[n], end = g_rowptr[n + 1];
    float inv = g_den[n * NHEADS + h];
    float acc = 0.f;
    for (int j = beg; j < end; j++) {
        int   s  = g_esrc[j];
        float al = g_alpha[(size_t)j * NHEADS + h];      // warp-broadcast
        acc += al * g_ht[(size_t)s * HID + tid];
    }
    float v = acc * inv + bias[tid];
    g_h[(size_t)n * HID + tid] = v > 0.f ? v : expm1f(v);
}

// ---------------- aggregation: F=2048 (d=256), fused mean + bias --------
// one block per node; thread k-strided across heads: f = k*256 + tid, h = k.
__global__ void __launch_bounds__(256)
aggr_csr_2048(const float* __restrict__ bias) {
    int n   = blockIdx.x;
    int tid = threadIdx.x;
    int beg = g_rowptr[n], end = g_rowptr[n + 1];
    float inv[NHEADS];
#pragma unroll
    for (int k = 0; k < NHEADS; k++) inv[k] = g_den[n * NHEADS + k];
    float acc[NHEADS];
#pragma unroll
    for (int k = 0; k < NHEADS; k++) acc[k] = 0.f;
    for (int j = beg; j < end; j++) {
        int s = g_esrc[j];
        const float* row = g_ht + (size_t)s * FMAX;
        const float* al  = g_alpha + (size_t)j * NHEADS;
#pragma unroll
        for (int k = 0; k < NHEADS; k++)
            acc[k] += al[k] * row[k * HID + tid];
    }
    float sum = 0.f;
#pragma unroll
    for (int k = 0; k < NHEADS; k++) sum += acc[k] * inv[k];
    g_h[(size_t)n * HID + tid] = sum * (1.f / NHEADS) + bias[tid];
}

// ---------------- classifier tail: [N,128] @ [128,2] + bias -------------
__global__ void classifier2(const float* __restrict__ wc2,
                            const float* __restrict__ bc2,
                            float* __restrict__ out) {
    int n = blockIdx.x * blockDim.x + threadIdx.x;
    if (n >= NN) return;
    float a0 = bc2[0], a1 = bc2[1];
    const float* r = g_c1 + (size_t)n * 128;
#pragma unroll 4
    for (int k = 0; k < 128; k++) {
        float v = r[k];
        a0 += v * wc2[k * 2 + 0];
        a1 += v * wc2[k * 2 + 1];
    }
    out[n * 2 + 0] = a0;
    out[n * 2 + 1] = a1;
}

// ---------------- host orchestration ----------------
static void run_gat_layer(const float* W, const float* asrc,
                          const float* adst, const float* bias, int d,
                          bool concat_elu, float* p_h, float* p_ht) {
    const int F = NHEADS * d;
    {
        dim3 grid((F + 127) / 128, (NN + 127) / 128);
        sgemm128<<<grid, 256>>>(p_h, W, p_ht, NN, HID, F, nullptr, 0);
    }
    {
        long threads = (long)NN * NHEADS * 32;
        scores_kernel<<<(unsigned)((threads + 255) / 256), 256>>>(asrc, adst, d);
    }
    softmax_csr<<<(NN * NHEADS + 255) / 256, 256>>>();
    if (concat_elu)
        aggr_csr_256<<<NN, 256>>>(bias);
    else
        aggr_csr_2048<<<NN, 256>>>(bias);
}

extern "C" void kernel_launch(void* const* d_in, const int* in_sizes, int n_in,
                              void* d_out, int out_size) {
    const float* x     = (const float*)d_in[0];
    const int*   ei    = (const int*)  d_in[1];
    const float* w_in  = (const float*)d_in[2];
    const float* b_in  = (const float*)d_in[3];
    const float* w0    = (const float*)d_in[4];
    const float* asrc0 = (const float*)d_in[5];
    const float* adst0 = (const float*)d_in[6];
    const float* b0    = (const float*)d_in[7];
    const float* w1    = (const float*)d_in[8];
    const float* asrc1 = (const float*)d_in[9];
    const float* adst1 = (const float*)d_in[10];
    const float* b1    = (const float*)d_in[11];
    const float* w2    = (const float*)d_in[12];
    const float* asrc2 = (const float*)d_in[13];
    const float* adst2 = (const float*)d_in[14];
    const float* b2    = (const float*)d_in[15];
    const float* wc1   = (const float*)d_in[16];
    const float* bc1   = (const float*)d_in[17];
    const float* wc2   = (const float*)d_in[18];
    const float* bc2   = (const float*)d_in[19];
    float* out = (float*)d_out;

    float *p_h, *p_ht, *p_c1;
    int   *p_deg;
    cudaGetSymbolAddress((void**)&p_h,   g_h);
    cudaGetSymbolAddress((void**)&p_ht,  g_ht);
    cudaGetSymbolAddress((void**)&p_c1,  g_c1);
    cudaGetSymbolAddress((void**)&p_deg, g_deg);

    // ---- CSR build (once; reused by all 3 layers) ----
    cudaMemsetAsync(p_deg, 0, NN * sizeof(int));
    deg_kernel<<<(ETOT + 255) / 256, 256>>>(ei);
    scan_kernel<<<1, 1024>>>();
    scatter_kernel<<<(ETOT + 255) / 256, 256>>>(ei);

    // ---- input linear: h = x @ w_in + b_in   [N,165] @ [165,256] ----
    {
        dim3 grid((HID + 127) / 128, (NN + 127) / 128);
        sgemm128<<<grid, 256>>>(x, w_in, p_h, NN, FIN, HID, b_in, 0);
    }

    run_gat_layer(w0, asrc0, adst0, b0, HID / NHEADS, true,  p_h, p_ht);
    run_gat_layer(w1, asrc1, adst1, b1, HID / NHEADS, true,  p_h, p_ht);
    run_gat_layer(w2, asrc2, adst2, b2, HID,          false, p_h, p_ht);

    // ---- classifier ----
    {
        dim3 grid((128 + 127) / 128, (NN + 127) / 128);
        sgemm128<<<grid, 256>>>(p_h, wc1, p_c1, NN, HID, 128, bc1, 1);
    }
    classifier2<<<(NN + 255) / 256, 256>>>(wc2, bc2, out);
}

// round 3
// speedup vs baseline: 2.1556x; 2.1556x over previous
#include <cuda_runtime.h>
#include <cuda_bf16.h>
#include <math.h>
#include <stdint.h>

#define NN     50000
#define EE     400000
#define ETOT   (EE + NN)     // edges + self loops
#define FIN    165
#define HID    256
#define NHEADS 8
#define FMAX   2048          // 8 heads * 256

// ---------------- scratch (device globals; no allocation) ----------------
__device__ float g_h    [NN * HID];        // current node features
__device__ float g_ht   [NN * FMAX];       // transformed / aggregated features
__device__ float g_ssrc [NN * NHEADS];
__device__ float g_sdst [NN * NHEADS];
__device__ float g_den  [NN * NHEADS];     // 1/denominator per (node, head)
__device__ float g_alpha[ETOT * NHEADS];   // exp(e - m), CSR slot order
__device__ float g_c1   [NN * 128];        // classifier hidden
__device__ float g_u    [NHEADS * HID];    // layer2 projected a_src
__device__ float g_v    [NHEADS * HID];    // layer2 projected a_dst
__device__ float g_b2t  [FMAX * HID];      // layer2 rearranged weight (x0.125)
// CSR
__device__ int   g_deg   [NN];
__device__ int   g_rowptr[NN + 1];
__device__ int   g_wpos  [NN];
__device__ int   g_esrc  [ETOT];

__device__ __forceinline__ float leaky(float v) { return v > 0.f ? v : 0.2f * v; }
__device__ __forceinline__ float to_tf32(float x) {
    float r;
    asm("cvt.rna.tf32.f32 %0, %1;" : "=f"(r) : "f"(x));
    return r;
}

// =================== TF32 tensor-core GEMM =============================
// C[M,N] = A[M,K] @ B[K,N] (+bias, act). Block 128x128, BK=16, 256 thr.
// 8 warps in 2x4 layout, each warp 64x32 via mma.m16n8k8.tf32.
#define BM 128
#define BN 128
#define BK 16
#define ASTR (BK + 4)    // 20 -> conflict-free A frag loads
#define BSTR (BN + 8)    // 136 -> conflict-free B frag loads

__global__ void __launch_bounds__(256, 2)
gemm_tf32(const float* __restrict__ A, const float* __restrict__ B,
          float* __restrict__ C, int M, int K, int N,
          const float* __restrict__ bias, int act /*0 none,1 relu*/) {
    __shared__ float As[2][BM][ASTR];   // [m][k]
    __shared__ float Bs[2][BK][BSTR];   // [k][n]

    const int tid  = threadIdx.x;
    const int lane = tid & 31;
    const int warp = tid >> 5;
    const int wrow = warp >> 2;          // 0..1
    const int wcol = warp & 3;           // 0..3
    const int g    = lane >> 2;          // 0..7
    const int tg   = lane & 3;           // 0..3
    const int brow = blockIdx.y * BM;
    const int bcol = blockIdx.x * BN;

    float c[4][4][4];
#pragma unroll
    for (int i = 0; i < 4; i++)
#pragma unroll
        for (int j = 0; j < 4; j++)
#pragma unroll
            for (int k = 0; k < 4; k++) c[i][j][k] = 0.f;

    const int kTiles = (K + BK - 1) / BK;

    // prologue: load tile 0 into buf 0
    {
        const int k0 = 0;
#pragma unroll
        for (int i = 0; i < 8; i++) {
            int lin = i * 256 + tid;
            int m = lin >> 4, kk = lin & 15;
            float v = 0.f;
            if (brow + m < M && k0 + kk < K) v = A[(size_t)(brow + m) * K + k0 + kk];
            As[0][m][kk] = to_tf32(v);
        }
#pragma unroll
        for (int i = 0; i < 8; i++) {
            int lin = i * 256 + tid;
            int kk = lin >> 7, n = lin & 127;
            float v = 0.f;
            if (k0 + kk < K && bcol + n < N) v = B[(size_t)(k0 + kk) * N + bcol + n];
            Bs[0][kk][n] = to_tf32(v);
        }
    }
    __syncthreads();

    for (int t = 0; t < kTiles; t++) {
        const int cbuf = t & 1;
        const int nbuf = cbuf ^ 1;
        float stA[8], stB[8];
        const bool pf = (t + 1 < kTiles);
        if (pf) {
            const int k0 = (t + 1) * BK;
#pragma unroll
            for (int i = 0; i < 8; i++) {
                int lin = i * 256 + tid;
                int m = lin >> 4, kk = lin & 15;
                float v = 0.f;
                if (brow + m < M && k0 + kk < K) v = A[(size_t)(brow + m) * K + k0 + kk];
                stA[i] = v;
            }
#pragma unroll
            for (int i = 0; i < 8; i++) {
                int lin = i * 256 + tid;
                int kk = lin >> 7, n = lin & 127;
                float v = 0.f;
                if (k0 + kk < K && bcol + n < N) v = B[(size_t)(k0 + kk) * N + bcol + n];
                stB[i] = v;
            }
        }

        // compute on cbuf: 2 k-steps of 8
#pragma unroll
        for (int ks = 0; ks < BK; ks += 8) {
            uint32_t a[4][4], b[4][2];
#pragma unroll
            for (int mt = 0; mt < 4; mt++) {
                int mr = wrow * 64 + mt * 16;
                a[mt][0] = __float_as_uint(As[cbuf][mr + g][ks + tg]);
                a[mt][1] = __float_as_uint(As[cbuf][mr + g + 8][ks + tg]);
                a[mt][2] = __float_as_uint(As[cbuf][mr + g][ks + tg + 4]);
                a[mt][3] = __float_as_uint(As[cbuf][mr + g + 8][ks + tg + 4]);
            }
#pragma unroll
            for (int nt = 0; nt < 4; nt++) {
                int nc = wcol * 32 + nt * 8;
                b[nt][0] = __float_as_uint(Bs[cbuf][ks + tg][nc + g]);
                b[nt][1] = __float_as_uint(Bs[cbuf][ks + tg + 4][nc + g]);
            }
#pragma unroll
            for (int mt = 0; mt < 4; mt++)
#pragma unroll
                for (int nt = 0; nt < 4; nt++) {
                    asm volatile(
                        "mma.sync.aligned.m16n8k8.row.col.f32.tf32.tf32.f32 "
                        "{%0,%1,%2,%3}, {%4,%5,%6,%7}, {%8,%9}, {%0,%1,%2,%3};\n"
                        : "+f"(c[mt][nt][0]), "+f"(c[mt][nt][1]),
                          "+f"(c[mt][nt][2]), "+f"(c[mt][nt][3])
                        : "r"(a[mt][0]), "r"(a[mt][1]), "r"(a[mt][2]), "r"(a[mt][3]),
                          "r"(b[nt][0]), "r"(b[nt][1]));
                }
        }

        if (pf) {
#pragma unroll
            for (int i = 0; i < 8; i++) {
                int lin = i * 256 + tid;
                int m = lin >> 4, kk = lin & 15;
                As[nbuf][m][kk] = to_tf32(stA[i]);
            }
#pragma unroll
            for (int i = 0; i < 8; i++) {
                int lin = i * 256 + tid;
                int kk = lin >> 7, n = lin & 127;
                Bs[nbuf][kk][n] = to_tf32(stB[i]);
            }
        }
        __syncthreads();
    }

    // epilogue
#pragma unroll
    for (int mt = 0; mt < 4; mt++) {
        int r0 = brow + wrow * 64 + mt * 16 + g;
        int r1 = r0 + 8;
#pragma unroll
        for (int nt = 0; nt < 4; nt++) {
            int c0col = bcol + wcol * 32 + nt * 8 + 2 * tg;
            float bv0 = 0.f, bv1 = 0.f;
            if (bias) { bv0 = bias[c0col]; bv1 = bias[c0col + 1]; }
            float v00 = c[mt][nt][0] + bv0, v01 = c[mt][nt][1] + bv1;
            float v10 = c[mt][nt][2] + bv0, v11 = c[mt][nt][3] + bv1;
            if (act == 1) {
                v00 = fmaxf(v00, 0.f); v01 = fmaxf(v01, 0.f);
                v10 = fmaxf(v10, 0.f); v11 = fmaxf(v11, 0.f);
            }
            if (r0 < M) { C[(size_t)r0 * N + c0col] = v00; C[(size_t)r0 * N + c0col + 1] = v01; }
            if (r1 < M) { C[(size_t)r1 * N + c0col] = v10; C[(size_t)r1 * N + c0col + 1] = v11; }
        }
    }
}

// ---------------- CSR build ----------------
__global__ void deg_kernel(const int* __restrict__ ei) {
    int e = blockIdx.x * blockDim.x + threadIdx.x;
    if (e >= ETOT) return;
    int t = (e < EE) ? ei[EE + e] : (e - EE);
    atomicAdd(&g_deg[t], 1);
}

__global__ void scan_kernel() {
    __shared__ int sh[1024];
    __shared__ int running;
    if (threadIdx.x == 0) running = 0;
    __syncthreads();
    for (int base = 0; base < NN; base += 1024) {
        int i = base + (int)threadIdx.x;
        int v = (i < NN) ? g_deg[i] : 0;
        sh[threadIdx.x] = v;
        __syncthreads();
        for (int off = 1; off < 1024; off <<= 1) {
            int t = (threadIdx.x >= off) ? sh[threadIdx.x - off] : 0;
            __syncthreads();
            sh[threadIdx.x] += t;
            __syncthreads();
        }
        int incl = sh[threadIdx.x];
        int excl = incl - v + running;
        if (i < NN) { g_rowptr[i] = excl; g_wpos[i] = excl; }
        __syncthreads();
        if (threadIdx.x == 0) running += sh[1023];
        __syncthreads();
    }
    if (threadIdx.x == 0) g_rowptr[NN] = running;
}

__global__ void scatter_kernel(const int* __restrict__ ei) {
    int e = blockIdx.x * blockDim.x + threadIdx.x;
    if (e >= ETOT) return;
    int s = (e < EE) ? ei[e]      : (e - EE);
    int t = (e < EE) ? ei[EE + e] : (e - EE);
    int slot = atomicAdd(&g_wpos[t], 1);
    g_esrc[slot] = s;
}

// ---------------- per-(node,head) attention scores ----------------
// warp per (node, head). slice=1: dot h-th d-slice; slice=0: dot full row.
__global__ void scores_kernel(const float* __restrict__ feat, int fstride,
                              const float* __restrict__ asrc,
                              const float* __restrict__ adst,
                              int d, int slice) {
    int gt   = blockIdx.x * blockDim.x + threadIdx.x;
    int warp = gt >> 5;
    int lane = gt & 31;
    if (warp >= NN * NHEADS) return;
    int n = warp / NHEADS, h = warp % NHEADS;
    const float* row = feat + (size_t)n * fstride + (slice ? h * d : 0);
    float s1 = 0.f, s2 = 0.f;
    for (int i = lane; i < d; i += 32) {
        float v = row[i];
        s1 += v * asrc[h * d + i];
        s2 += v * adst[h * d + i];
    }
#pragma unroll
    for (int o = 16; o; o >>= 1) {
        s1 += __shfl_xor_sync(0xFFFFFFFFu, s1, o);
        s2 += __shfl_xor_sync(0xFFFFFFFFu, s2, o);
    }
    if (lane == 0) {
        g_ssrc[n * NHEADS + h] = s1;
        g_sdst[n * NHEADS + h] = s2;
    }
}

// ---------------- segment softmax, atomic-free ----------------
__global__ void softmax_csr() {
    int idx = blockIdx.x * blockDim.x + threadIdx.x;
    if (idx >= NN * NHEADS) return;
    int n = idx / NHEADS, h = idx % NHEADS;
    int beg = g_rowptr[n], end = g_rowptr[n + 1];
    float sd = g_sdst[idx];
    float mx = -1e30f;
    for (int j = beg; j < end; j++) {
        float v = leaky(g_ssrc[g_esrc[j] * NHEADS + h] + sd);
        mx = fmaxf(mx, v);
    }
    float den = 0.f;
    for (int j = beg; j < end; j++) {
        float v  = leaky(g_ssrc[g_esrc[j] * NHEADS + h] + sd);
        float ex = expf(v - mx);
        g_alpha[(size_t)j * NHEADS + h] = ex;
        den += ex;
    }
    g_den[idx] = 1.f / den;
}

// ---------------- layers 0/1 aggregation (d=32), fused bias+ELU ---------
__global__ void __launch_bounds__(256)
aggr_csr_256(const float* __restrict__ bias) {
    int n   = blockIdx.x;
    int tid = threadIdx.x;
    int h   = tid >> 5;
    int beg = g_rowptr[n], end = g_rowptr[n + 1];
    float inv = g_den[n * NHEADS + h];
    float acc = 0.f;
    for (int j = beg; j < end; j++) {
        int   s  = g_esrc[j];
        float al = g_alpha[(size_t)j * NHEADS + h];
        acc += al * g_ht[(size_t)s * HID + tid];
    }
    float v = acc * inv + bias[tid];
    g_h[(size_t)n * HID + tid] = v > 0.f ? v : expm1f(v);
}

// ---------------- layer2: aggregate RAW x per head -> g_ht [N,2048] -----
__global__ void __launch_bounds__(256)
aggr2_raw() {
    int n   = blockIdx.x;
    int tid = threadIdx.x;
    int beg = g_rowptr[n], end = g_rowptr[n + 1];
    float acc[NHEADS];
#pragma unroll
    for (int k = 0; k < NHEADS; k++) acc[k] = 0.f;
    for (int j = beg; j < end; j++) {
        int s = g_esrc[j];
        float v = g_h[(size_t)s * HID + tid];
        const float* al = g_alpha + (size_t)j * NHEADS;
#pragma unroll
        for (int k = 0; k < NHEADS; k++) acc[k] += al[k] * v;
    }
#pragma unroll
    for (int k = 0; k < NHEADS; k++) {
        float inv = g_den[n * NHEADS + k];
        g_ht[(size_t)n * FMAX + k * HID + tid] = acc[k] * inv;
    }
}

// ---------------- layer2 pre-projection: u,v and W2' --------------------
__global__ void compute_uv(const float* __restrict__ w2,
                           const float* __restrict__ a_s,
                           const float* __restrict__ a_d) {
    int t = blockIdx.x * blockDim.x + threadIdx.x;
    if (t >= 2 * NHEADS * HID) return;
    int sel = t / (NHEADS * HID);
    int h = (t / HID) % NHEADS;
    int i = t % HID;
    const float* av   = (sel ? a_d : a_s) + h * HID;
    const float* wrow = w2 + (size_t)i * FMAX + h * HID;
    float s = 0.f;
    for (int j = 0; j < HID; j++) s += wrow[j] * av[j];
    (sel ? g_v : g_u)[h * HID + i] = s;
}

__global__ void transpose_b2(const float* __restrict__ w2) {
    int t = blockIdx.x * blockDim.x + threadIdx.x;
    if (t >= FMAX * HID) return;
    int k = t / HID;          // h*256 + i
    int j = t % HID;
    int h = k / HID, i = k % HID;
    g_b2t[t] = w2[(size_t)i * FMAX + h * HID + j] * 0.125f;
}

// ---------------- classifier tail: [N,128] @ [128,2] + bias -------------
__global__ void classifier2(const float* __restrict__ wc2,
                            const float* __restrict__ bc2,
                            float* __restrict__ out) {
    int n = blockIdx.x * blockDim.x + threadIdx.x;
    if (n >= NN) return;
    float a0 = bc2[0], a1 = bc2[1];
    const float* r = g_c1 + (size_t)n * 128;
#pragma unroll 4
    for (int k = 0; k < 128; k++) {
        float v = r[k];
        a0 += v * wc2[k * 2 + 0];
        a1 += v * wc2[k * 2 + 1];
    }
    out[n * 2 + 0] = a0;
    out[n * 2 + 1] = a1;
}

// ---------------- host orchestration ----------------
static inline void launch_gemm(const float* A, const float* B, float* C,
                               int M, int K, int N, const float* bias, int act) {
    dim3 grid((N + BN - 1) / BN, (M + BM - 1) / BM);
    gemm_tf32<<<grid, 256>>>(A, B, C, M, K, N, bias, act);
}

extern "C" void kernel_launch(void* const* d_in, const int* in_sizes, int n_in,
                              void* d_out, int out_size) {
    const float* x     = (const float*)d_in[0];
    const int*   ei    = (const int*)  d_in[1];
    const float* w_in  = (const float*)d_in[2];
    const float* b_in  = (const float*)d_in[3];
    const float* w0    = (const float*)d_in[4];
    const float* asrc0 = (const float*)d_in[5];
    const float* adst0 = (const float*)d_in[6];
    const float* b0    = (const float*)d_in[7];
    const float* w1    = (const float*)d_in[8];
    const float* asrc1 = (const float*)d_in[9];
    const float* adst1 = (const float*)d_in[10];
    const float* b1    = (const float*)d_in[11];
    const float* w2    = (const float*)d_in[12];
    const float* asrc2 = (const float*)d_in[13];
    const float* adst2 = (const float*)d_in[14];
    const float* b2    = (const float*)d_in[15];
    const float* wc1   = (const float*)d_in[16];
    const float* bc1   = (const float*)d_in[17];
    const float* wc2   = (const float*)d_in[18];
    const float* bc2   = (const float*)d_in[19];
    float* out = (float*)d_out;

    float *p_h, *p_ht, *p_c1, *p_b2t, *p_u, *p_v;
    int   *p_deg;
    cudaGetSymbolAddress((void**)&p_h,   g_h);
    cudaGetSymbolAddress((void**)&p_ht,  g_ht);
    cudaGetSymbolAddress((void**)&p_c1,  g_c1);
    cudaGetSymbolAddress((void**)&p_b2t, g_b2t);
    cudaGetSymbolAddress((void**)&p_u,   g_u);
    cudaGetSymbolAddress((void**)&p_v,   g_v);
    cudaGetSymbolAddress((void**)&p_deg, g_deg);

    // ---- CSR build (once; reused by all 3 layers) ----
    cudaMemsetAsync(p_deg, 0, NN * sizeof(int));
    deg_kernel<<<(ETOT + 255) / 256, 256>>>(ei);
    scan_kernel<<<1, 1024>>>();
    scatter_kernel<<<(ETOT + 255) / 256, 256>>>(ei);

    // ---- input linear ----
    launch_gemm(x, w_in, p_h, NN, FIN, HID, b_in, 0);

    const unsigned score_grid = (unsigned)(((long)NN * NHEADS * 32 + 255) / 256);

    // ---- layers 0 and 1 ----
    const float* Ws[2]  = {w0, w1};
    const float* As_[2] = {asrc0, asrc1};
    const float* Ad_[2] = {adst0, adst1};
    const float* Bs_[2] = {b0, b1};
    for (int l = 0; l < 2; l++) {
        launch_gemm(p_h, Ws[l], p_ht, NN, HID, HID, nullptr, 0);
        scores_kernel<<<score_grid, 256>>>(p_ht, HID, As_[l], Ad_[l],
                                           HID / NHEADS, 1);
        softmax_csr<<<(NN * NHEADS + 255) / 256, 256>>>();
        aggr_csr_256<<<NN, 256>>>(Bs_[l]);
    }

    // ---- layer 2 (restructured: aggregate raw x, then K=2048 GEMM) ----
    compute_uv<<<(2 * NHEADS * HID + 255) / 256, 256>>>(w2, asrc2, adst2);
    transpose_b2<<<(FMAX * HID + 255) / 256, 256>>>(w2);
    scores_kernel<<<score_grid, 256>>>(p_h, HID, p_u, p_v, HID, 0);
    softmax_csr<<<(NN * NHEADS + 255) / 256, 256>>>();
    aggr2_raw<<<NN, 256>>>();
    launch_gemm(p_ht, p_b2t, p_h, NN, FMAX, HID, b2, 0);

    // ---- classifier ----
    launch_gemm(p_h, wc1, p_c1, NN, HID, 128, bc1, 1);
    classifier2<<<(NN + 255) / 256, 256>>>(wc2, bc2, out);
}